// round 1
// baseline (speedup 1.0000x reference)
#include <cuda_runtime.h>

#define NA 8192
#define NN 65536
#define NE 262144
#define D  128
#define NB 2
#define TILE 32
#define EPS 1e-5f

// ---------------- scratch (device globals; no allocation allowed) ------------
__device__ float g_q[NA * D];    // relu(GN(actors @ Wq^T)) table
__device__ float g_a[NA * D];    // actors @ Wagt^T, accumulates edge messages
__device__ float g_x[NA * D];    // relu(GN(a))
__device__ float g_act[NA * D];  // inter-block actors

// =============================================================================
// Tiled GEMM: out[TILE][128] = in[TILE][K] @ W[128][K]^T
// 256 threads; thread (jb = tid&31, eb = tid>>5) computes 4x4 micro-tile.
// W staged per 32-k chunk into sW[kk][j] (transposed) in shared.
// sW and sOut may alias (write happens after a final sync).
// =============================================================================
template <int K, int SSTR>
__device__ __forceinline__ void tile_gemm(const float* __restrict__ W,
                                          const float* sIn, float* sOut,
                                          float* sW) {
    const int tid = threadIdx.x;
    const int jb = tid & 31;   // columns jb*4 .. jb*4+3
    const int eb = tid >> 5;   // rows    eb*4 .. eb*4+3
    float acc[4][4];
#pragma unroll
    for (int i = 0; i < 4; i++)
#pragma unroll
        for (int j = 0; j < 4; j++) acc[i][j] = 0.0f;

    for (int k0 = 0; k0 < K; k0 += 32) {
        __syncthreads();  // protect sW (and aliased sOut) from previous readers
        {
            // stage: sW[kk*128 + j] = W[j*K + k0 + kk]
            const int j = tid >> 1;
            const int kk0 = (tid & 1) << 4;
            const float4* Wr = reinterpret_cast<const float4*>(W + j * K + k0 + kk0);
#pragma unroll
            for (int i = 0; i < 4; i++) {
                float4 v = Wr[i];
                int kk = kk0 + i * 4;
                sW[kk * 128 + j]       = v.x;
                sW[(kk + 1) * 128 + j] = v.y;
                sW[(kk + 2) * 128 + j] = v.z;
                sW[(kk + 3) * 128 + j] = v.w;
            }
        }
        __syncthreads();
#pragma unroll
        for (int kk = 0; kk < 32; kk += 4) {
            float4 a4[4];
#pragma unroll
            for (int i = 0; i < 4; i++)
                a4[i] = *reinterpret_cast<const float4*>(sIn + (eb * 4 + i) * SSTR + k0 + kk);
#pragma unroll
            for (int t = 0; t < 4; t++) {
                float4 bv = *reinterpret_cast<const float4*>(sW + (kk + t) * 128 + jb * 4);
#pragma unroll
                for (int i = 0; i < 4; i++) {
                    float av = (t == 0) ? a4[i].x : (t == 1) ? a4[i].y
                             : (t == 2) ? a4[i].z : a4[i].w;
                    acc[i][0] = fmaf(av, bv.x, acc[i][0]);
                    acc[i][1] = fmaf(av, bv.y, acc[i][1]);
                    acc[i][2] = fmaf(av, bv.z, acc[i][2]);
                    acc[i][3] = fmaf(av, bv.w, acc[i][3]);
                }
            }
        }
    }
    __syncthreads();  // all sW reads done before (possibly aliased) sOut write
#pragma unroll
    for (int i = 0; i < 4; i++) {
        float4 v = make_float4(acc[i][0], acc[i][1], acc[i][2], acc[i][3]);
        *reinterpret_cast<float4*>(sOut + (eb * 4 + i) * 128 + jb * 4) = v;
    }
}

// GroupNorm (1 group over 128 channels) per row of sOut -> sDst[row*stride + c]
__device__ __forceinline__ void tile_gn_to_smem(const float* sOut,
                                                const float* __restrict__ g,
                                                const float* __restrict__ bb,
                                                float* sDst, int dstStride,
                                                bool doRelu) {
    const int tid = threadIdx.x;
    const int warp = tid >> 5, lane = tid & 31;
    const float g0 = g[lane], g1 = g[lane + 32], g2 = g[lane + 64], g3 = g[lane + 96];
    const float b0 = bb[lane], b1 = bb[lane + 32], b2 = bb[lane + 64], b3 = bb[lane + 96];
    for (int e = warp; e < TILE; e += 8) {
        float v0 = sOut[e * 128 + lane];
        float v1 = sOut[e * 128 + lane + 32];
        float v2 = sOut[e * 128 + lane + 64];
        float v3 = sOut[e * 128 + lane + 96];
        float s = v0 + v1 + v2 + v3;
        float q = fmaf(v0, v0, fmaf(v1, v1, fmaf(v2, v2, v3 * v3)));
#pragma unroll
        for (int o = 16; o > 0; o >>= 1) {
            s += __shfl_xor_sync(0xffffffffu, s, o);
            q += __shfl_xor_sync(0xffffffffu, q, o);
        }
        float mu = s * (1.0f / 128.0f);
        float rs = rsqrtf(q * (1.0f / 128.0f) - mu * mu + EPS);
        float y0 = (v0 - mu) * rs * g0 + b0;
        float y1 = (v1 - mu) * rs * g1 + b1;
        float y2 = (v2 - mu) * rs * g2 + b2;
        float y3 = (v3 - mu) * rs * g3 + b3;
        if (doRelu) {
            y0 = fmaxf(y0, 0.0f); y1 = fmaxf(y1, 0.0f);
            y2 = fmaxf(y2, 0.0f); y3 = fmaxf(y3, 0.0f);
        }
        sDst[e * dstStride + lane]      = y0;
        sDst[e * dstStride + lane + 32] = y1;
        sDst[e * dstStride + lane + 64] = y2;
        sDst[e * dstStride + lane + 96] = y3;
    }
}

// =============================================================================
// Fused edge kernel: per 32-edge tile
//   h = relu(d2 @ W0^T + b0)
//   d = relu(GN(h @ W1^T))
//   u = relu(GN([d,q,c] @ Wc0^T))
//   m = u @ Wc1^T
//   atomicAdd(g_a[hi], m)
// shared: sIn[TILE][384] (concat buffer), sWO[32][128] (W-chunk / output union)
// =============================================================================
__global__ void __launch_bounds__(256) edge_kernel(
    const float* __restrict__ actor_ctrs, const float* __restrict__ node_ctrs,
    const int* __restrict__ hi, const int* __restrict__ wi,
    const float* __restrict__ nodes,
    const float* __restrict__ W0, const float* __restrict__ b0,
    const float* __restrict__ W1, const float* __restrict__ g1, const float* __restrict__ b1,
    const float* __restrict__ Wc0, const float* __restrict__ gc0, const float* __restrict__ bc0,
    const float* __restrict__ Wc1) {
    extern __shared__ float smem[];
    float* sIn = smem;               // TILE*384
    float* sWO = smem + TILE * 384;  // 32*128 (sW and sOut union)
    __shared__ int sHi[TILE], sWi[TILE];
    __shared__ float sW0[2 * D], sB0[D];

    const int tid = threadIdx.x;
    const int e0 = blockIdx.x * TILE;

    if (tid < TILE) { sHi[tid] = hi[e0 + tid]; sWi[tid] = wi[e0 + tid]; }
    sW0[tid] = W0[tid];  // 256 threads == 2*D
    if (tid < D) sB0[tid] = b0[tid];
    __syncthreads();

    // stage: h -> sIn[:,0:128], q -> sIn[:,128:256], c -> sIn[:,256:384]
    {
        const int e = tid >> 3;     // 0..31
        const int seg = tid & 7;    // 0..7, 16 floats each
        const int h = sHi[e], w = sWi[e];
        const float dx = actor_ctrs[h * 2]     - node_ctrs[w * 2];
        const float dy = actor_ctrs[h * 2 + 1] - node_ctrs[w * 2 + 1];
        const float4* qr = reinterpret_cast<const float4*>(g_q + h * D) + seg * 4;
        const float4* cr = reinterpret_cast<const float4*>(nodes + w * D) + seg * 4;
        float4* dq = reinterpret_cast<float4*>(sIn + e * 384 + 128) + seg * 4;
        float4* dc = reinterpret_cast<float4*>(sIn + e * 384 + 256) + seg * 4;
#pragma unroll
        for (int i = 0; i < 4; i++) { dq[i] = qr[i]; dc[i] = cr[i]; }
#pragma unroll
        for (int i = 0; i < 16; i++) {
            int k = seg * 16 + i;
            float hv = fmaf(dx, sW0[2 * k], fmaf(dy, sW0[2 * k + 1], sB0[k]));
            sIn[e * 384 + k] = fmaxf(hv, 0.0f);
        }
    }
    __syncthreads();

    tile_gemm<128, 384>(W1, sIn, sWO, sWO);          // t = h @ W1^T
    __syncthreads();
    tile_gn_to_smem(sWO, g1, b1, sIn, 384, true);    // d -> sIn[:,0:128]
    __syncthreads();
    tile_gemm<384, 384>(Wc0, sIn, sWO, sWO);         // [d,q,c] @ Wc0^T
    __syncthreads();
    tile_gn_to_smem(sWO, gc0, bc0, sIn, 384, true);  // u -> sIn[:,0:128]
    __syncthreads();
    tile_gemm<128, 384>(Wc1, sIn, sWO, sWO);         // m = u @ Wc1^T
    __syncthreads();

    // scatter-add into g_a
    {
        const int e = tid >> 3, seg = tid & 7;
        const int h = sHi[e];
        float* dst = g_a + h * D + seg * 16;
        const float* src = sWO + e * 128 + seg * 16;
#pragma unroll
        for (int i = 0; i < 16; i++) atomicAdd(dst + i, src[i]);
    }
}

// =============================================================================
// Actor-side row GEMM: out = f(in @ W^T), optional GN / relu / +res.
// For C2 (lin): out = relu(GN(x@W^T) + res). For q: relu(GN(..)). For agt: raw.
// =============================================================================
template <bool GN, bool RELU, bool RES>
__global__ void __launch_bounds__(256) rowgemm_kernel(
    const float* __restrict__ in, const float* __restrict__ W,
    const float* __restrict__ g, const float* __restrict__ bb,
    const float* __restrict__ res, float* __restrict__ out) {
    __shared__ float sIn[TILE * 128];
    __shared__ float sWO[32 * 128];
    const int tid = threadIdx.x;
    const int r0 = blockIdx.x * TILE;
    {
        const int r = tid >> 3, seg = tid & 7;
        const float4* src = reinterpret_cast<const float4*>(in + (r0 + r) * D) + seg * 4;
        float4* dst = reinterpret_cast<float4*>(sIn + r * 128) + seg * 4;
#pragma unroll
        for (int i = 0; i < 4; i++) dst[i] = src[i];
    }
    __syncthreads();
    tile_gemm<128, 128>(W, sIn, sWO, sWO);
    __syncthreads();
    if (GN) {
        const int warp = tid >> 5, lane = tid & 31;
        const float gg0 = g[lane], gg1 = g[lane + 32], gg2 = g[lane + 64], gg3 = g[lane + 96];
        const float bb0 = bb[lane], bb1 = bb[lane + 32], bb2 = bb[lane + 64], bb3 = bb[lane + 96];
        for (int e = warp; e < TILE; e += 8) {
            float v0 = sWO[e * 128 + lane];
            float v1 = sWO[e * 128 + lane + 32];
            float v2 = sWO[e * 128 + lane + 64];
            float v3 = sWO[e * 128 + lane + 96];
            float s = v0 + v1 + v2 + v3;
            float q = fmaf(v0, v0, fmaf(v1, v1, fmaf(v2, v2, v3 * v3)));
#pragma unroll
            for (int o = 16; o > 0; o >>= 1) {
                s += __shfl_xor_sync(0xffffffffu, s, o);
                q += __shfl_xor_sync(0xffffffffu, q, o);
            }
            float mu = s * (1.0f / 128.0f);
            float rs = rsqrtf(q * (1.0f / 128.0f) - mu * mu + EPS);
            float y0 = (v0 - mu) * rs * gg0 + bb0;
            float y1 = (v1 - mu) * rs * gg1 + bb1;
            float y2 = (v2 - mu) * rs * gg2 + bb2;
            float y3 = (v3 - mu) * rs * gg3 + bb3;
            const long rb = (long)(r0 + e) * D;
            if (RES) {
                y0 += res[rb + lane];      y1 += res[rb + lane + 32];
                y2 += res[rb + lane + 64]; y3 += res[rb + lane + 96];
            }
            if (RELU) {
                y0 = fmaxf(y0, 0.0f); y1 = fmaxf(y1, 0.0f);
                y2 = fmaxf(y2, 0.0f); y3 = fmaxf(y3, 0.0f);
            }
            out[rb + lane]      = y0;
            out[rb + lane + 32] = y1;
            out[rb + lane + 64] = y2;
            out[rb + lane + 96] = y3;
        }
    } else {
        const int r = tid >> 3, seg = tid & 7;
        float4* dst = reinterpret_cast<float4*>(out + (r0 + r) * D) + seg * 4;
        const float4* src = reinterpret_cast<const float4*>(sWO + r * 128) + seg * 4;
#pragma unroll
        for (int i = 0; i < 4; i++) dst[i] = src[i];
    }
}

// C1: x = relu(GN(a)) ; one warp per row
__global__ void __launch_bounds__(256) gnrows_kernel(
    const float* __restrict__ in, const float* __restrict__ g,
    const float* __restrict__ bb, float* __restrict__ out) {
    const int lane = threadIdx.x & 31;
    const int row = blockIdx.x * 8 + (threadIdx.x >> 5);
    const float* x = in + (long)row * D;
    float v0 = x[lane], v1 = x[lane + 32], v2 = x[lane + 64], v3 = x[lane + 96];
    float s = v0 + v1 + v2 + v3;
    float q = fmaf(v0, v0, fmaf(v1, v1, fmaf(v2, v2, v3 * v3)));
#pragma unroll
    for (int o = 16; o > 0; o >>= 1) {
        s += __shfl_xor_sync(0xffffffffu, s, o);
        q += __shfl_xor_sync(0xffffffffu, q, o);
    }
    float mu = s * (1.0f / 128.0f);
    float rs = rsqrtf(q * (1.0f / 128.0f) - mu * mu + EPS);
    float* o_ = out + (long)row * D;
    o_[lane]      = fmaxf((v0 - mu) * rs * g[lane] + bb[lane], 0.0f);
    o_[lane + 32] = fmaxf((v1 - mu) * rs * g[lane + 32] + bb[lane + 32], 0.0f);
    o_[lane + 64] = fmaxf((v2 - mu) * rs * g[lane + 64] + bb[lane + 64], 0.0f);
    o_[lane + 96] = fmaxf((v3 - mu) * rs * g[lane + 96] + bb[lane + 96], 0.0f);
}

#define EDGE_SMEM ((TILE * 384 + 32 * 128) * 4)

extern "C" void kernel_launch(void* const* d_in, const int* in_sizes, int n_in,
                              void* d_out, int out_size) {
    (void)in_sizes; (void)n_in; (void)out_size;
    const float* actors     = (const float*)d_in[0];
    const float* nodes      = (const float*)d_in[1];
    const float* actor_ctrs = (const float*)d_in[2];
    const float* node_ctrs  = (const float*)d_in[3];
    const int*   hi         = (const int*)d_in[4];
    const int*   wi         = (const int*)d_in[5];
    const float* dist0_W = (const float*)d_in[6];
    const float* dist0_b = (const float*)d_in[7];
    const float* dist1_W = (const float*)d_in[8];
    const float* dist1_g = (const float*)d_in[9];
    const float* dist1_b = (const float*)d_in[10];
    const float* query_W = (const float*)d_in[11];
    const float* query_g = (const float*)d_in[12];
    const float* query_b = (const float*)d_in[13];
    const float* ctx0_W  = (const float*)d_in[14];
    const float* ctx0_g  = (const float*)d_in[15];
    const float* ctx0_b  = (const float*)d_in[16];
    const float* ctx1_W  = (const float*)d_in[17];
    const float* agt_W   = (const float*)d_in[18];
    const float* norm_g  = (const float*)d_in[19];
    const float* norm_b  = (const float*)d_in[20];
    const float* lin_W   = (const float*)d_in[21];
    const float* lin_g   = (const float*)d_in[22];
    const float* lin_b   = (const float*)d_in[23];
    float* outp = (float*)d_out;

    void *pq_, *pa_, *px_, *pact_;
    cudaGetSymbolAddress(&pq_, g_q);
    cudaGetSymbolAddress(&pa_, g_a);
    cudaGetSymbolAddress(&px_, g_x);
    cudaGetSymbolAddress(&pact_, g_act);
    float* p_q   = (float*)pq_;
    float* p_a   = (float*)pa_;
    float* p_x   = (float*)px_;
    float* p_act = (float*)pact_;

    cudaFuncSetAttribute(edge_kernel, cudaFuncAttributeMaxDynamicSharedMemorySize, EDGE_SMEM);

    for (int i = 0; i < NB; i++) {
        const float* cur = (i == 0) ? actors : p_act;
        float* nxt = (i == NB - 1) ? outp : p_act;

        // q table: relu(GN(actors @ Wq^T))
        rowgemm_kernel<true, true, false><<<NA / TILE, 256>>>(
            cur, query_W + i * D * D, query_g + i * D, query_b + i * D, nullptr, p_q);
        // a = actors @ Wagt^T
        rowgemm_kernel<false, false, false><<<NA / TILE, 256>>>(
            cur, agt_W + i * D * D, nullptr, nullptr, nullptr, p_a);
        // fused edge chain + scatter-add into a
        edge_kernel<<<NE / TILE, 256, EDGE_SMEM>>>(
            actor_ctrs, node_ctrs, hi, wi, nodes,
            dist0_W + i * D * 2, dist0_b + i * D,
            dist1_W + i * D * D, dist1_g + i * D, dist1_b + i * D,
            ctx0_W + i * D * 3 * D, ctx0_g + i * D, ctx0_b + i * D,
            ctx1_W + i * D * D);
        // x = relu(GN(a))
        gnrows_kernel<<<NA / 8, 256>>>(p_a, norm_g + i * D, norm_b + i * D, p_x);
        // out = relu(GN(x @ Wlin^T) + res)
        rowgemm_kernel<true, true, true><<<NA / TILE, 256>>>(
            p_x, lin_W + i * D * D, lin_g + i * D, lin_b + i * D, cur, nxt);
    }
}